// round 15
// baseline (speedup 1.0000x reference)
#include <cuda_runtime.h>
#include <math.h>

#define T_LEN 131072
#define NB 16
#define NCHA 2
#define NSEQ (NB*NCHA)
#define NBS 48
#define DB2L 0.16609640474436813f   // log2(10)/20

// Q layout per plane: t -> chunk c = t>>10 (128), quad q4 = (t&1023)>>2 (256), lane t&3
//   float4 index = q4*128 + c
#define LNC 128
#define Q4C 256
#define P4  32768          // float4 per plane

#define BQ_NT 512
#define BQ_LEV 9
#define SM_W 16            // warmup segments (16 x 1024 = 16384 samples)

__device__ float g_xd  [NSEQ*T_LEN];
__device__ float g_low [NSEQ*T_LEN];
__device__ float g_high[NSEQ*T_LEN];
__device__ float g_ga  [NBS*T_LEN];     // at * signed gain
__device__ float g_gr  [NBS*T_LEN];     // rt * signed gain
__device__ float g_gsm [NBS*T_LEN];     // smoothed gains (raw domain)
__device__ float g_xm  [NSEQ*T_LEN];
__device__ float g_da  [NB*T_LEN];      // at * signed limiter detector
__device__ float g_dr  [NB*T_LEN];      // rt * signed limiter detector
__device__ float g_lg  [NB*T_LEN];

struct BQ  { float na1, na2, b0, k1, k2; };
struct SMC { float A1, A2, AA11, AAX, AA22; };

__device__ __forceinline__ float f_lg2(float x){ float r; asm("lg2.approx.f32 %0,%1;":"=f"(r):"f"(x)); return r; }
__device__ __forceinline__ float f_ex2(float x){ float r; asm("ex2.approx.f32 %0,%1;":"=f"(r):"f"(x)); return r; }

__device__ __forceinline__ SMC make_smc(float at, float rt)
{
    SMC s; s.A1=1.f-at; s.A2=1.f-rt;
    s.AA11=s.A1*s.A1; s.AAX=s.A1*s.A2; s.AA22=s.A2*s.A2;
    return s;
}

// ---------------- dist: natural -> Q, tanh drive mix ----------------
__global__ void k_dist(const float* __restrict__ x, const float* __restrict__ drive,
                       const float* __restrict__ dmix)
{
    __shared__ float4 sT[32][33];
    __shared__ float sw, sgd;
    int s = blockIdx.y, b = s >> 1;
    int bx = blockIdx.x;
    int c0 = (bx >> 3) * 32, q0 = (bx & 7) * 32;
    int tx = threadIdx.x, ty = threadIdx.y;
    if (tx == 0 && ty == 0) { sw = dmix[b]; sgd = exp2f(drive[b] * DB2L); }
    __syncthreads();
    float w = sw, gd = sgd, ow = 1.f - w;
    const float4* xin = (const float4*)x + (size_t)s * P4;
    float4 v = __ldg(xin + (c0 + ty) * Q4C + q0 + tx);
#define TL(L) { \
    float z = fminf(fmaxf(v.L * gd, -15.f), 15.f); \
    float e = __expf(2.f * z); \
    float th = __fdividef(e - 1.f, e + 1.f); \
    v.L = fmaf(w, th, ow * v.L); }
    TL(x) TL(y) TL(z) TL(w)
#undef TL
    sT[ty][tx] = v;
    __syncthreads();
    float4* xo = (float4*)g_xd + (size_t)s * P4;
    xo[(q0 + ty) * LNC + c0 + tx] = sT[tx][ty];
}

// ---------------- fused LR4 biquad ----------------
__device__ __forceinline__ void bqstep(float x, float& z1, float& z2, const BQ& c)
{
    float t  = fmaf(c.k1, x, z2);
    float n2 = fmaf(c.na2, z1, c.k2 * x);
    z1 = fmaf(c.na1, z1, t);
    z2 = n2;
}
__device__ __forceinline__ float bqstep_y(float x, float& z1, float& z2, const BQ& c)
{
    float y  = fmaf(c.b0, x, z1);
    float t  = fmaf(c.k1, x, z2);
    float n2 = fmaf(c.na2, z1, c.k2 * x);
    z1 = fmaf(c.na1, z1, t);
    z2 = n2;
    return y;
}

__device__ __forceinline__ float2 ks_scan(float2 my, float2* sF, float (*sP)[4], int tid)
{
    __syncthreads();
#pragma unroll
    for (int lv = 0; lv < BQ_LEV; ++lv) {
        sF[tid] = my;
        __syncthreads();
        int d = 1 << lv;
        if (tid >= d) {
            float2 o = sF[tid - d];
            my.x += sP[lv][0]*o.x + sP[lv][1]*o.y;
            my.y += sP[lv][2]*o.x + sP[lv][3]*o.y;
        }
        __syncthreads();
    }
    sF[tid] = my;
    __syncthreads();
    float2 e = (tid > 0) ? sF[tid-1] : make_float2(0.f, 0.f);
    __syncthreads();
    return e;
}

__global__ void k_bq(const float* __restrict__ locut, const float* __restrict__ hicut)
{
    __shared__ float2 sF[BQ_NT];
    __shared__ float  sP[BQ_LEV][4];
    __shared__ BQ     sCF;
    int blk = blockIdx.x;
    int f = blk >> 5, s = blk & 31, b = s >> 1;
    const float4* in4 = (const float4*)g_xd + (size_t)s * P4;
    float4* out4 = (float4*)(f ? g_high : g_low) + (size_t)s * P4;
    int tid = threadIdx.x;

    if (tid == 0) {
        double cut = f ? (double)hicut[b] : (double)locut[b];
        double w0 = 2.0 * 3.14159265358979323846 * cut / 44100.0;
        double al = sin(w0) * 0.70710678118654752;
        double c  = cos(w0);
        double b0, b1, b2;
        if (f == 0) { b0 = (1.0 - c)*0.5; b1 = 1.0 - c;    b2 = (1.0 - c)*0.5; }
        else        { b0 = (1.0 + c)*0.5; b1 = -(1.0 + c); b2 = (1.0 + c)*0.5; }
        double a0 = 1.0 + al;
        b0 /= a0; b1 /= a0; b2 /= a0;
        double a1 = -2.0*c/a0, a2 = (1.0 - al)/a0;
        sCF.na1 = (float)(-a1); sCF.na2 = (float)(-a2); sCF.b0 = (float)b0;
        sCF.k1 = (float)(b1 - a1*b0); sCF.k2 = (float)(b2 - a2*b0);
        double m00 = -a1, m01 = 1.0, m10 = -a2, m11 = 0.0;
        for (int k = 0; k < 8; ++k) {          // A^256
            double t00 = m00*m00 + m01*m10, t01 = m00*m01 + m01*m11;
            double t10 = m10*m00 + m11*m10, t11 = m10*m01 + m11*m11;
            m00 = t00; m01 = t01; m10 = t10; m11 = t11;
        }
        for (int lv = 0; lv < BQ_LEV; ++lv) {
            sP[lv][0] = (float)m00; sP[lv][1] = (float)m01;
            sP[lv][2] = (float)m10; sP[lv][3] = (float)m11;
            double t00 = m00*m00 + m01*m10, t01 = m00*m01 + m01*m11;
            double t10 = m10*m00 + m11*m10, t11 = m10*m01 + m11*m11;
            m00 = t00; m01 = t01; m10 = t10; m11 = t11;
        }
    }
    __syncthreads();
    BQ cf = sCF;
    const float4* ip = in4 + (tid & 3) * 64 * LNC + (tid >> 2);
    float4 ring[8];

#define BQ_BODY(STMT) \
    { _Pragma("unroll") for (int j = 0; j < 8; ++j) ring[j] = __ldg(ip + j*LNC); } \
    for (int bs = 0; bs < 56; bs += 8) { \
        _Pragma("unroll") for (int j = 0; j < 8; ++j) { \
            float4 xv = ring[j]; ring[j] = __ldg(ip + (bs + 8 + j)*LNC); \
            int jp = bs + j; (void)jp; STMT; } } \
    { int bs = 56; \
      _Pragma("unroll") for (int j = 0; j < 8; ++j) { \
            float4 xv = ring[j]; int jp = bs + j; (void)jp; STMT; } }

    float z1 = 0.f, z2 = 0.f;
    BQ_BODY({ bqstep(xv.x, z1, z2, cf); bqstep(xv.y, z1, z2, cf);
              bqstep(xv.z, z1, z2, cf); bqstep(xv.w, z1, z2, cf); })
    float2 e1 = ks_scan(make_float2(z1, z2), sF, sP, tid);

    z1 = e1.x; z2 = e1.y;
    float w1 = 0.f, w2 = 0.f;
    BQ_BODY({ bqstep(bqstep_y(xv.x, z1, z2, cf), w1, w2, cf);
              bqstep(bqstep_y(xv.y, z1, z2, cf), w1, w2, cf);
              bqstep(bqstep_y(xv.z, z1, z2, cf), w1, w2, cf);
              bqstep(bqstep_y(xv.w, z1, z2, cf), w1, w2, cf); })
    float2 e2 = ks_scan(make_float2(w1, w2), sF, sP, tid);

    z1 = e1.x; z2 = e1.y; w1 = e2.x; w2 = e2.y;
    float4* op = out4 + (tid & 3) * 64 * LNC + (tid >> 2);
    BQ_BODY({ float4 r;
              r.x = bqstep_y(bqstep_y(xv.x, z1, z2, cf), w1, w2, cf);
              r.y = bqstep_y(bqstep_y(xv.y, z1, z2, cf), w1, w2, cf);
              r.z = bqstep_y(bqstep_y(xv.z, z1, z2, cf), w1, w2, cf);
              r.w = bqstep_y(bqstep_y(xv.w, z1, z2, cf), w1, w2, cf);
              op[jp*LNC] = r; })
#undef BQ_BODY
}

// ---------------- band gain: emits pre-scaled SIGNED gain streams ----------------
struct GP { float ct, sc, et, se; };
__device__ __forceinline__ float comp_gain(float det, const GP& p)
{
    float xdb = 6.0205999132796239f * f_lg2(fmaxf(det, 1e-7f));
    float gdb = fminf(fminf(p.sc * (p.ct - xdb), p.se * (p.et - xdb)), 0.f);
    return f_ex2(gdb * DB2L);
}

__global__ void k_bandgain(const float* __restrict__ ct, const float* __restrict__ cr,
                           const float* __restrict__ et, const float* __restrict__ er,
                           const float* __restrict__ atms, const float* __restrict__ rtms)
{
    __shared__ GP sp[3];
    __shared__ float sat[3], srt[3];   // signed at, rt (sgn folded)
    int b = blockIdx.y;
    int tid = threadIdx.x;
    if (tid < 3) {
        int idx = b*3 + tid;
        GP g; g.ct = ct[idx]; g.sc = 1.f - 1.f/cr[idx];
        g.et = et[idx]; g.se = 1.f - 1.f/er[idx];
        sp[tid] = g;
        float at = 1.f - __expf(-2200.f/(atms[idx]*44100.f));
        float rt = 1.f - __expf(-2200.f/(rtms[idx]*44100.f));
        float sg = (at >= rt) ? 1.f : -1.f;   // attack_on_rise=False -> min iff at>=rt
        sat[tid] = sg * at; srt[tid] = sg * rt;
    }
    __syncthreads();
    int i = blockIdx.x * blockDim.x + tid;
    size_t p0 = (size_t)(b*2) * P4, p1 = p0 + P4;
    float4 x0 = ((const float4*)g_xd)[p0 + i],  x1 = ((const float4*)g_xd)[p1 + i];
    float4 l0 = ((const float4*)g_low)[p0 + i], l1 = ((const float4*)g_low)[p1 + i];
    float4 h0 = ((const float4*)g_high)[p0 + i],h1 = ((const float4*)g_high)[p1 + i];
    float4 gl, gm, gh;
#define GL(L) { float ls = l0.L + l1.L, hs = h0.L + h1.L, xs = x0.L + x1.L; \
    gl.L = comp_gain(fabsf(ls), sp[0]); \
    gm.L = comp_gain(fabsf(xs - ls - hs), sp[1]); \
    gh.L = comp_gain(fabsf(hs), sp[2]); }
    GL(x) GL(y) GL(z) GL(w)
#undef GL
#define EMIT(K, G) { \
    float a = sat[K], r = srt[K]; \
    float4 ga4, gr4; \
    ga4.x = a*G.x; ga4.y = a*G.y; ga4.z = a*G.z; ga4.w = a*G.w; \
    gr4.x = r*G.x; gr4.y = r*G.y; gr4.z = r*G.z; gr4.w = r*G.w; \
    ((float4*)g_ga)[(size_t)(K*NB + b)*P4 + i] = ga4; \
    ((float4*)g_gr)[(size_t)(K*NB + b)*P4 + i] = gr4; }
    EMIT(0, gl) EMIT(1, gm) EMIT(2, gh)
#undef EMIT
}

// ---------------- smoothing: pre-scaled streams, min-only signed domain ----------------
// ring depth 8 per stream -> ~64 ring regs, no spill (R14 fix)
template<bool STORE, bool LIM>
__device__ __forceinline__ float sm_seg2(const float4* __restrict__ ap,
                                         const float4* __restrict__ rp,
                                         float4* __restrict__ dp,
                                         float h, const SMC& s, float sgn, float lt)
{
    float4 ra[8], rr[8];
#pragma unroll
    for (int j = 0; j < 8; ++j) { ra[j] = __ldg(ap + j*LNC); rr[j] = __ldg(rp + j*LNC); }
#define SPAIR(AG0, RG0, AG1, RG1, H1V) { \
    float u11 = fmaf(s.A1, AG0, AG1); \
    float u21 = fmaf(s.A2, AG0, RG1); \
    float u12 = fmaf(s.A1, RG0, AG1); \
    float u22 = fmaf(s.A2, RG0, RG1); \
    float um  = fminf(u21, u12); \
    if (STORE) H1V = fminf(fmaf(s.A1, h, AG0), fmaf(s.A2, h, RG0)); \
    h = fminf(fmaf(s.AA11, h, u11), fminf(fmaf(s.AAX, h, um), fmaf(s.AA22, h, u22))); }
#define SQ2 { \
    float h1a = 0.f, h1b = 0.f; \
    SPAIR(av.x, rv.x, av.y, rv.y, h1a) \
    float hA = h; \
    SPAIR(av.z, rv.z, av.w, rv.w, h1b) \
    if (STORE) { \
        float4 o; \
        if (LIM) { \
            o.x = fminf(1.f, __fdividef(lt, fmaxf(sgn*h1a, 1e-7f))); \
            o.y = fminf(1.f, __fdividef(lt, fmaxf(sgn*hA , 1e-7f))); \
            o.z = fminf(1.f, __fdividef(lt, fmaxf(sgn*h1b, 1e-7f))); \
            o.w = fminf(1.f, __fdividef(lt, fmaxf(sgn*h  , 1e-7f))); \
        } else { o.x = sgn*h1a; o.y = sgn*hA; o.z = sgn*h1b; o.w = sgn*h; } \
        dp[jp*LNC] = o; } }
    for (int bs = 0; bs < Q4C-8; bs += 8) {
#pragma unroll
        for (int j = 0; j < 8; ++j) {
            float4 av = ra[j]; float4 rv = rr[j];
            ra[j] = __ldg(ap + (bs + 8 + j)*LNC);
            rr[j] = __ldg(rp + (bs + 8 + j)*LNC);
            int jp = bs + j; (void)jp;
            SQ2
        }
    }
    { int bs = Q4C-8;
#pragma unroll
      for (int j = 0; j < 8; ++j) {
          float4 av = ra[j]; float4 rv = rr[j];
          int jp = bs + j; (void)jp;
          SQ2
      } }
#undef SQ2
#undef SPAIR
    return h;
}

template<bool LIM>
__device__ __forceinline__ void sm_run2(const float* __restrict__ ga, const float* __restrict__ gr,
                                        float* __restrict__ dst, int c, const SMC& s,
                                        float sgn, float lt, float initv)
{
    const float4* ap = (const float4*)ga;
    const float4* rp = (const float4*)gr;
    float4* dp = (float4*)dst;
    float h = sgn * initv;
#pragma unroll 1
    for (int seg = 0; seg < SM_W; ++seg) {
        int cc = c - SM_W + seg;
        if (cc >= 0)
            h = sm_seg2<false, false>(ap + cc, rp + cc, dp, h, s, sgn, lt);
    }
    sm_seg2<true, LIM>(ap + c, rp + c, dp + c, h, s, sgn, lt);
}

// 48 blocks x 128 threads
__global__ void k_smooth_band(const float* __restrict__ atms, const float* __restrict__ rtms)
{
    int seq = blockIdx.x, c = threadIdx.x;      // c in [0,128)
    int band = seq >> 4, b = seq & 15;
    int idx = b*3 + band;
    float at = 1.f - __expf(-2200.f/(atms[idx]*44100.f));
    float rt = 1.f - __expf(-2200.f/(rtms[idx]*44100.f));
    float sgn = (at >= rt) ? 1.f : -1.f;
    SMC s = make_smc(at, rt);
    sm_run2<false>(g_ga + (size_t)seq*T_LEN, g_gr + (size_t)seq*T_LEN,
                   g_gsm + (size_t)seq*T_LEN, c, s, sgn, 0.f, 1.f);
}

// 16 blocks x 128 threads
__global__ void k_smooth_lim(const float* __restrict__ lth, const float* __restrict__ lat,
                             const float* __restrict__ lrt)
{
    int b = blockIdx.x, c = threadIdx.x;
    float at = 1.f - __expf(-2200.f/(lat[b]*44100.f));
    float rt = 1.f - __expf(-2200.f/(lrt[b]*44100.f));
    float sgn = (at <= rt) ? 1.f : -1.f;        // attack_on_rise=True -> min iff at<=rt
    float lt = exp2f(lth[b] * DB2L);
    SMC s = make_smc(at, rt);
    sm_run2<true>(g_da + (size_t)b*T_LEN, g_dr + (size_t)b*T_LEN,
                  g_lg + (size_t)b*T_LEN, c, s, sgn, lt, 0.f);
}

// ---------------- mix + pre-scaled SIGNED limiter detector ----------------
__global__ void k_mix(const float* __restrict__ mbmix, const float* __restrict__ lat,
                      const float* __restrict__ lrt)
{
    __shared__ float slat, slrt;   // signed at, rt
    int b = blockIdx.y;
    int tid = threadIdx.x;
    if (tid == 0) {
        float at = 1.f - __expf(-2200.f/(lat[b]*44100.f));
        float rt = 1.f - __expf(-2200.f/(lrt[b]*44100.f));
        float sg = (at <= rt) ? 1.f : -1.f;
        slat = sg * at; slrt = sg * rt;
    }
    __syncthreads();
    float mb = __ldg(mbmix + b), om = 1.f - mb;
    int i = blockIdx.x * blockDim.x + tid;
    size_t p0 = (size_t)(b*2) * P4, p1 = p0 + P4;
    float4 x0 = ((const float4*)g_xd)[p0 + i],  x1 = ((const float4*)g_xd)[p1 + i];
    float4 l0 = ((const float4*)g_low)[p0 + i], l1 = ((const float4*)g_low)[p1 + i];
    float4 h0 = ((const float4*)g_high)[p0 + i],h1 = ((const float4*)g_high)[p1 + i];
    float4 gl = ((const float4*)g_gsm)[(size_t)(0*NB + b)*P4 + i];
    float4 gm = ((const float4*)g_gsm)[(size_t)(1*NB + b)*P4 + i];
    float4 gh = ((const float4*)g_gsm)[(size_t)(2*NB + b)*P4 + i];
    float sa = slat, sr = slrt;
    float4 m0, m1, da, dr;
#define ML(L) { \
    float mid0 = x0.L - l0.L - h0.L; \
    float y0 = l0.L*gl.L + mid0*gm.L + h0.L*gh.L; \
    float a0 = mb*y0 + om*x0.L; \
    float mid1 = x1.L - l1.L - h1.L; \
    float y1 = l1.L*gl.L + mid1*gm.L + h1.L*gh.L; \
    float a1 = mb*y1 + om*x1.L; \
    m0.L = a0; m1.L = a1; \
    float d = fabsf(a0 + a1); \
    da.L = sa*d; dr.L = sr*d; }
    ML(x) ML(y) ML(z) ML(w)
#undef ML
    ((float4*)g_xm)[p0 + i] = m0;
    ((float4*)g_xm)[p1 + i] = m1;
    ((float4*)g_da)[(size_t)b*P4 + i] = da;
    ((float4*)g_dr)[(size_t)b*P4 + i] = dr;
}

// ---------------- final: Q -> natural, apply limiter gain ----------------
__global__ void k_final(float* __restrict__ out)
{
    __shared__ float4 sA[32][33], sB[32][33];
    int b = blockIdx.y;
    int bx = blockIdx.x;
    int c0 = (bx >> 3) * 32, q0 = (bx & 7) * 32;
    int tx = threadIdx.x, ty = threadIdx.y;
    size_t A = (size_t)(q0 + ty) * LNC + c0 + tx;
    const float4* lg4 = (const float4*)g_lg + (size_t)b * P4;
    const float4* xm4 = (const float4*)g_xm;
    float4 g  = __ldg(lg4 + A);
    float4 m0 = __ldg(xm4 + (size_t)(b*2)   * P4 + A);
    float4 m1 = __ldg(xm4 + (size_t)(b*2+1) * P4 + A);
    m0.x *= g.x; m0.y *= g.y; m0.z *= g.z; m0.w *= g.w;
    m1.x *= g.x; m1.y *= g.y; m1.z *= g.z; m1.w *= g.w;
    sA[tx][ty] = m0;
    sB[tx][ty] = m1;
    __syncthreads();
    float4* o0 = (float4*)out + (size_t)(b*2) * P4;
    float4* o1 = o0 + P4;
    size_t N = (size_t)(c0 + ty) * Q4C + q0 + tx;
    o0[N] = sA[ty][tx];
    o1[N] = sB[ty][tx];
}

// ---------------- launcher ----------------
extern "C" void kernel_launch(void* const* d_in, const int* in_sizes, int n_in,
                              void* d_out, int out_size)
{
    const float* x     = (const float*)d_in[0];
    const float* drive = (const float*)d_in[1];
    const float* dmix  = (const float*)d_in[2];
    const float* locut = (const float*)d_in[3];
    const float* hicut = (const float*)d_in[4];
    const float* mbmix = (const float*)d_in[5];
    const float* ct    = (const float*)d_in[6];
    const float* cr    = (const float*)d_in[7];
    const float* et    = (const float*)d_in[8];
    const float* er    = (const float*)d_in[9];
    const float* atms  = (const float*)d_in[10];
    const float* rtms  = (const float*)d_in[11];
    const float* lth   = (const float*)d_in[12];
    const float* lat   = (const float*)d_in[13];
    const float* lrt   = (const float*)d_in[14];
    (void)in_sizes; (void)n_in; (void)out_size;

    dim3 tile(32, 32);
    k_dist<<<dim3(32, NSEQ), tile>>>(x, drive, dmix);
    k_bq<<<64, BQ_NT>>>(locut, hicut);
    k_bandgain<<<dim3(128, NB), 256>>>(ct, cr, et, er, atms, rtms);
    k_smooth_band<<<NBS, LNC>>>(atms, rtms);
    k_mix<<<dim3(128, NB), 256>>>(mbmix, lat, lrt);
    k_smooth_lim<<<NB, LNC>>>(lth, lat, lrt);
    k_final<<<dim3(32, NB), tile>>>((float*)d_out);
}

// round 16
// speedup vs baseline: 1.4671x; 1.4671x over previous
#include <cuda_runtime.h>
#include <math.h>

#define T_LEN 131072
#define NB 16
#define NCHA 2
#define NSEQ (NB*NCHA)
#define NBS 48
#define DB2L 0.16609640474436813f   // log2(10)/20

// Q layout per plane: t -> chunk c = t>>10 (128), quad q4 = (t&1023)>>2 (256), lane t&3
//   float4 index = q4*128 + c
#define LNC 128
#define Q4C 256
#define P4  32768          // float4 per plane
#define G8  16384          // 8-sample groups per plane (128 rows x 128 chunks)

#define BQ_NT 512
#define BQ_LEV 9
#define SM_W 16            // warmup segments (16 x 1024 = 16384 samples)

__device__ float g_xd  [NSEQ*T_LEN];
__device__ float g_low [NSEQ*T_LEN];
__device__ float g_high[NSEQ*T_LEN];
__device__ float g_gin [NBS*T_LEN];     // SIGNED gains (sgn*gain)
__device__ float g_gsm [NBS*T_LEN];
__device__ float g_xm  [NSEQ*T_LEN];
__device__ float g_det [NB*T_LEN];      // SIGNED limiter detector
__device__ float g_lg  [NB*T_LEN];
// 8-step composed maps: 9 intercepts per 8-sample group, [r*128 + c] indexing
__device__ float4 g_m8a[NBS*G8];
__device__ float4 g_m8b[NBS*G8];
__device__ float  g_m8c[NBS*G8];
__device__ float4 g_l8a[NB*G8];
__device__ float4 g_l8b[NB*G8];
__device__ float  g_l8c[NB*G8];

struct BQ  { float na1, na2, b0, k1, k2; };
struct SMC { float at, rt, A1, A2, AA11, AAX, AA22; };

__device__ __forceinline__ float f_lg2(float x){ float r; asm("lg2.approx.f32 %0,%1;":"=f"(r):"f"(x)); return r; }
__device__ __forceinline__ float f_ex2(float x){ float r; asm("ex2.approx.f32 %0,%1;":"=f"(r):"f"(x)); return r; }

__device__ __forceinline__ SMC make_smc(float at, float rt)
{
    SMC s; s.at=at; s.rt=rt; s.A1=1.f-at; s.A2=1.f-rt;
    s.AA11=s.A1*s.A1; s.AAX=s.A1*s.A2; s.AA22=s.A2*s.A2;
    return s;
}

// V∘U for (N+1)-piece min-affine maps; S = slopes of V (S[i] = A1^(N-i) A2^i)
template<int N>
__device__ __forceinline__ void composeN(const float* u, const float* v, const float* S, float* w)
{
#pragma unroll
    for (int k = 0; k <= 2*N; ++k) {
        float m = 0.f;
        bool first = true;
#pragma unroll
        for (int i = 0; i <= N; ++i) {
            int j = k - i;
            if (j < 0 || j > N) continue;
            float t = fmaf(S[i], u[j], v[i]);
            m = first ? t : fminf(m, t);
            first = false;
        }
        w[k] = m;
    }
}

// 2-step map from (g0,g1) signed
__device__ __forceinline__ void map2(const SMC& s, float g0, float g1, float* p)
{
    float t0 = s.at*g0, t1 = s.rt*g0, s0 = s.at*g1, s1 = s.rt*g1;
    p[0] = fmaf(s.A1, t0, s0);
    p[1] = fminf(fmaf(s.A2, t0, s1), fmaf(s.A1, t1, s0));
    p[2] = fmaf(s.A2, t1, s1);
}

// ---------------- dist: natural -> Q, tanh drive mix ----------------
__global__ void k_dist(const float* __restrict__ x, const float* __restrict__ drive,
                       const float* __restrict__ dmix)
{
    __shared__ float4 sT[32][33];
    __shared__ float sw, sgd;
    int s = blockIdx.y, b = s >> 1;
    int bx = blockIdx.x;
    int c0 = (bx >> 3) * 32, q0 = (bx & 7) * 32;
    int tx = threadIdx.x, ty = threadIdx.y;
    if (tx == 0 && ty == 0) { sw = dmix[b]; sgd = exp2f(drive[b] * DB2L); }
    __syncthreads();
    float w = sw, gd = sgd, ow = 1.f - w;
    const float4* xin = (const float4*)x + (size_t)s * P4;
    float4 v = __ldg(xin + (c0 + ty) * Q4C + q0 + tx);
#define TL(L) { \
    float z = fminf(fmaxf(v.L * gd, -15.f), 15.f); \
    float e = __expf(2.f * z); \
    float th = __fdividef(e - 1.f, e + 1.f); \
    v.L = fmaf(w, th, ow * v.L); }
    TL(x) TL(y) TL(z) TL(w)
#undef TL
    sT[ty][tx] = v;
    __syncthreads();
    float4* xo = (float4*)g_xd + (size_t)s * P4;
    xo[(q0 + ty) * LNC + c0 + tx] = sT[tx][ty];
}

// ---------------- fused LR4 biquad ----------------
__device__ __forceinline__ void bqstep(float x, float& z1, float& z2, const BQ& c)
{
    float t  = fmaf(c.k1, x, z2);
    float n2 = fmaf(c.na2, z1, c.k2 * x);
    z1 = fmaf(c.na1, z1, t);
    z2 = n2;
}
__device__ __forceinline__ float bqstep_y(float x, float& z1, float& z2, const BQ& c)
{
    float y  = fmaf(c.b0, x, z1);
    float t  = fmaf(c.k1, x, z2);
    float n2 = fmaf(c.na2, z1, c.k2 * x);
    z1 = fmaf(c.na1, z1, t);
    z2 = n2;
    return y;
}

__device__ __forceinline__ float2 ks_scan(float2 my, float2* sF, float (*sP)[4], int tid)
{
    __syncthreads();
#pragma unroll
    for (int lv = 0; lv < BQ_LEV; ++lv) {
        sF[tid] = my;
        __syncthreads();
        int d = 1 << lv;
        if (tid >= d) {
            float2 o = sF[tid - d];
            my.x += sP[lv][0]*o.x + sP[lv][1]*o.y;
            my.y += sP[lv][2]*o.x + sP[lv][3]*o.y;
        }
        __syncthreads();
    }
    sF[tid] = my;
    __syncthreads();
    float2 e = (tid > 0) ? sF[tid-1] : make_float2(0.f, 0.f);
    __syncthreads();
    return e;
}

__global__ void k_bq(const float* __restrict__ locut, const float* __restrict__ hicut)
{
    __shared__ float2 sF[BQ_NT];
    __shared__ float  sP[BQ_LEV][4];
    __shared__ BQ     sCF;
    int blk = blockIdx.x;
    int f = blk >> 5, s = blk & 31, b = s >> 1;
    const float4* in4 = (const float4*)g_xd + (size_t)s * P4;
    float4* out4 = (float4*)(f ? g_high : g_low) + (size_t)s * P4;
    int tid = threadIdx.x;

    if (tid == 0) {
        double cut = f ? (double)hicut[b] : (double)locut[b];
        double w0 = 2.0 * 3.14159265358979323846 * cut / 44100.0;
        double al = sin(w0) * 0.70710678118654752;
        double c  = cos(w0);
        double b0, b1, b2;
        if (f == 0) { b0 = (1.0 - c)*0.5; b1 = 1.0 - c;    b2 = (1.0 - c)*0.5; }
        else        { b0 = (1.0 + c)*0.5; b1 = -(1.0 + c); b2 = (1.0 + c)*0.5; }
        double a0 = 1.0 + al;
        b0 /= a0; b1 /= a0; b2 /= a0;
        double a1 = -2.0*c/a0, a2 = (1.0 - al)/a0;
        sCF.na1 = (float)(-a1); sCF.na2 = (float)(-a2); sCF.b0 = (float)b0;
        sCF.k1 = (float)(b1 - a1*b0); sCF.k2 = (float)(b2 - a2*b0);
        double m00 = -a1, m01 = 1.0, m10 = -a2, m11 = 0.0;
        for (int k = 0; k < 8; ++k) {          // A^256
            double t00 = m00*m00 + m01*m10, t01 = m00*m01 + m01*m11;
            double t10 = m10*m00 + m11*m10, t11 = m10*m01 + m11*m11;
            m00 = t00; m01 = t01; m10 = t10; m11 = t11;
        }
        for (int lv = 0; lv < BQ_LEV; ++lv) {
            sP[lv][0] = (float)m00; sP[lv][1] = (float)m01;
            sP[lv][2] = (float)m10; sP[lv][3] = (float)m11;
            double t00 = m00*m00 + m01*m10, t01 = m00*m01 + m01*m11;
            double t10 = m10*m00 + m11*m10, t11 = m10*m01 + m11*m11;
            m00 = t00; m01 = t01; m10 = t10; m11 = t11;
        }
    }
    __syncthreads();
    BQ cf = sCF;
    const float4* ip = in4 + (tid & 3) * 64 * LNC + (tid >> 2);
    float4 ring[8];

#define BQ_BODY(STMT) \
    { _Pragma("unroll") for (int j = 0; j < 8; ++j) ring[j] = __ldg(ip + j*LNC); } \
    for (int bs = 0; bs < 56; bs += 8) { \
        _Pragma("unroll") for (int j = 0; j < 8; ++j) { \
            float4 xv = ring[j]; ring[j] = __ldg(ip + (bs + 8 + j)*LNC); \
            int jp = bs + j; (void)jp; STMT; } } \
    { int bs = 56; \
      _Pragma("unroll") for (int j = 0; j < 8; ++j) { \
            float4 xv = ring[j]; int jp = bs + j; (void)jp; STMT; } }

    float z1 = 0.f, z2 = 0.f;
    BQ_BODY({ bqstep(xv.x, z1, z2, cf); bqstep(xv.y, z1, z2, cf);
              bqstep(xv.z, z1, z2, cf); bqstep(xv.w, z1, z2, cf); })
    float2 e1 = ks_scan(make_float2(z1, z2), sF, sP, tid);

    z1 = e1.x; z2 = e1.y;
    float w1 = 0.f, w2 = 0.f;
    BQ_BODY({ bqstep(bqstep_y(xv.x, z1, z2, cf), w1, w2, cf);
              bqstep(bqstep_y(xv.y, z1, z2, cf), w1, w2, cf);
              bqstep(bqstep_y(xv.z, z1, z2, cf), w1, w2, cf);
              bqstep(bqstep_y(xv.w, z1, z2, cf), w1, w2, cf); })
    float2 e2 = ks_scan(make_float2(w1, w2), sF, sP, tid);

    z1 = e1.x; z2 = e1.y; w1 = e2.x; w2 = e2.y;
    float4* op = out4 + (tid & 3) * 64 * LNC + (tid >> 2);
    BQ_BODY({ float4 r;
              r.x = bqstep_y(bqstep_y(xv.x, z1, z2, cf), w1, w2, cf);
              r.y = bqstep_y(bqstep_y(xv.y, z1, z2, cf), w1, w2, cf);
              r.z = bqstep_y(bqstep_y(xv.z, z1, z2, cf), w1, w2, cf);
              r.w = bqstep_y(bqstep_y(xv.w, z1, z2, cf), w1, w2, cf);
              op[jp*LNC] = r; })
#undef BQ_BODY
}

// ---------------- band gain: elementwise, emits SIGNED gains ----------------
struct GP { float ct, sc, et, se; };
__device__ __forceinline__ float comp_gain(float det, const GP& p)
{
    float xdb = 6.0205999132796239f * f_lg2(fmaxf(det, 1e-7f));
    float gdb = fminf(fminf(p.sc * (p.ct - xdb), p.se * (p.et - xdb)), 0.f);
    return f_ex2(gdb * DB2L);
}

__global__ void k_bandgain(const float* __restrict__ ct, const float* __restrict__ cr,
                           const float* __restrict__ et, const float* __restrict__ er,
                           const float* __restrict__ atms, const float* __restrict__ rtms)
{
    __shared__ GP  sp[3];
    __shared__ float ssg[3];
    int b = blockIdx.y;
    int tid = threadIdx.x;
    if (tid < 3) {
        int idx = b*3 + tid;
        GP g; g.ct = ct[idx]; g.sc = 1.f - 1.f/cr[idx];
        g.et = et[idx]; g.se = 1.f - 1.f/er[idx];
        sp[tid] = g;
        float at = 1.f - __expf(-2200.f/(atms[idx]*44100.f));
        float rt = 1.f - __expf(-2200.f/(rtms[idx]*44100.f));
        ssg[tid] = (at >= rt) ? 1.f : -1.f;   // attack_on_rise=False -> min iff at>=rt
    }
    __syncthreads();
    int i = blockIdx.x * blockDim.x + tid;
    size_t p0 = (size_t)(b*2) * P4, p1 = p0 + P4;
    float4 x0 = ((const float4*)g_xd)[p0 + i],  x1 = ((const float4*)g_xd)[p1 + i];
    float4 l0 = ((const float4*)g_low)[p0 + i], l1 = ((const float4*)g_low)[p1 + i];
    float4 h0 = ((const float4*)g_high)[p0 + i],h1 = ((const float4*)g_high)[p1 + i];
    float4 gl, gm, gh;
#define GL(L) { float ls = l0.L + l1.L, hs = h0.L + h1.L, xs = x0.L + x1.L; \
    gl.L = comp_gain(fabsf(ls), sp[0]); \
    gm.L = comp_gain(fabsf(xs - ls - hs), sp[1]); \
    gh.L = comp_gain(fabsf(hs), sp[2]); }
    GL(x) GL(y) GL(z) GL(w)
#undef GL
#define EMIT(K, G) { \
    float sg = ssg[K]; \
    float4 gg; gg.x = sg*G.x; gg.y = sg*G.y; gg.z = sg*G.z; gg.w = sg*G.w; \
    ((float4*)g_gin)[(size_t)(K*NB + b)*P4 + i] = gg; }
    EMIT(0, gl) EMIT(1, gm) EMIT(2, gh)
#undef EMIT
}

// ---------------- 8-map builders ----------------
__device__ __forceinline__ void build8(const SMC& s, const float* g /*8 signed*/, float* W /*9*/)
{
    float S2[3], S4[5];
    S2[0] = s.AA11; S2[1] = s.AAX; S2[2] = s.AA22;
    S4[0] = s.AA11*s.AA11; S4[1] = s.AA11*s.AAX; S4[2] = s.AAX*s.AAX;
    S4[3] = s.AAX*s.AA22;  S4[4] = s.AA22*s.AA22;
    float P[4][3];
#pragma unroll
    for (int p = 0; p < 4; ++p) map2(s, g[2*p], g[2*p+1], P[p]);
    float M4a[5], M4b[5];
    composeN<2>(P[0], P[1], S2, M4a);
    composeN<2>(P[2], P[3], S2, M4b);
    composeN<4>(M4a, M4b, S4, W);
}

__device__ __forceinline__ void mapbuild8(const float* __restrict__ src,
                                          float4* __restrict__ ma, float4* __restrict__ mb,
                                          float* __restrict__ mc, const SMC& s, int gi)
{
    int c = gi & 127, r = gi >> 7;           // r in [0,128): 8-sample row within chunk
    const float4* gp = (const float4*)src;
    float4 qa = __ldg(gp + (2*r)*LNC + c);
    float4 qb = __ldg(gp + (2*r + 1)*LNC + c);
    float g[8] = {qa.x, qa.y, qa.z, qa.w, qb.x, qb.y, qb.z, qb.w};
    float W[9];
    build8(s, g, W);
    ma[gi] = make_float4(W[0], W[1], W[2], W[3]);
    mb[gi] = make_float4(W[4], W[5], W[6], W[7]);
    mc[gi] = W[8];
}

__global__ void k_map8B(const float* __restrict__ atms, const float* __restrict__ rtms)
{
    int seq = blockIdx.y;
    int gi = blockIdx.x * blockDim.x + threadIdx.x;   // [0, 16384)
    int band = seq >> 4, b = seq & 15;
    int idx = b*3 + band;
    float at = 1.f - __expf(-2200.f/(atms[idx]*44100.f));
    float rt = 1.f - __expf(-2200.f/(rtms[idx]*44100.f));
    SMC s = make_smc(at, rt);
    mapbuild8(g_gin + (size_t)seq*T_LEN, g_m8a + (size_t)seq*G8,
              g_m8b + (size_t)seq*G8, g_m8c + (size_t)seq*G8, s, gi);
}

__global__ void k_map8L(const float* __restrict__ lat, const float* __restrict__ lrt)
{
    int b = blockIdx.y;
    int gi = blockIdx.x * blockDim.x + threadIdx.x;
    float at = 1.f - __expf(-2200.f/(lat[b]*44100.f));
    float rt = 1.f - __expf(-2200.f/(lrt[b]*44100.f));
    SMC s = make_smc(at, rt);
    mapbuild8(g_det + (size_t)b*T_LEN, g_l8a + (size_t)b*G8,
              g_l8b + (size_t)b*G8, g_l8c + (size_t)b*G8, s, gi);
}

// ---------------- smoothing: 8-map warmup + exact store segment ----------------
__device__ float warm8(const float4* __restrict__ ma, const float4* __restrict__ mb,
                       const float* __restrict__ mc, float h, const float* __restrict__ R)
{
    float4 ra[8], rb[8]; float rc[8];
#pragma unroll
    for (int j = 0; j < 8; ++j) {
        ra[j] = __ldg(ma + j*LNC); rb[j] = __ldg(mb + j*LNC); rc[j] = __ldg(mc + j*LNC);
    }
#define W8EVAL { \
    float t0 = fmaf(R[0], h, a.x), t1 = fmaf(R[1], h, a.y); \
    float t2 = fmaf(R[2], h, a.z), t3 = fmaf(R[3], h, a.w); \
    float t4 = fmaf(R[4], h, bb.x), t5 = fmaf(R[5], h, bb.y); \
    float t6 = fmaf(R[6], h, bb.z), t7 = fmaf(R[7], h, bb.w); \
    float t8 = fmaf(R[8], h, e); \
    float m01 = fminf(t0, t1), m23 = fminf(t2, t3); \
    float m45 = fminf(t4, t5), m67 = fminf(t6, t7); \
    h = fminf(fminf(fminf(m01, m23), fminf(m45, m67)), t8); }
    for (int bs = 0; bs < 120; bs += 8) {
#pragma unroll
        for (int j = 0; j < 8; ++j) {
            float4 a = ra[j], bb = rb[j]; float e = rc[j];
            ra[j] = __ldg(ma + (bs + 8 + j)*LNC);
            rb[j] = __ldg(mb + (bs + 8 + j)*LNC);
            rc[j] = __ldg(mc + (bs + 8 + j)*LNC);
            W8EVAL
        }
    }
#pragma unroll
    for (int j = 0; j < 8; ++j) {
        float4 a = ra[j], bb = rb[j]; float e = rc[j];
        W8EVAL
    }
#undef W8EVAL
    return h;
}

__device__ __forceinline__ float pair_min(float h, float g0, float g1, float* h1, const SMC& s)
{
    float t0 = s.at*g0, t1 = s.rt*g0, s0 = s.at*g1, s1 = s.rt*g1;
    float u11 = fmaf(s.A1,t0,s0), u21 = fmaf(s.A2,t0,s1);
    float u12 = fmaf(s.A1,t1,s0), u22 = fmaf(s.A2,t1,s1);
    float um  = fminf(u21, u12);
    *h1 = fminf(fmaf(s.A1,h,t0), fmaf(s.A2,h,t1));
    return fminf(fmaf(s.AA11,h,u11), fminf(fmaf(s.AAX,h,um), fmaf(s.AA22,h,u22)));
}

template<bool LIM>
__device__ __forceinline__ void store_seg(const float4* __restrict__ sp4, float4* __restrict__ dp,
                                          float h, const SMC& s, float sgn, float lt)
{
    float4 ring[16];
#pragma unroll
    for (int j = 0; j < 16; ++j) ring[j] = __ldg(sp4 + j*LNC);
#define SQ { float h1a, h1b; \
    float hA = pair_min(h, gv.x, gv.y, &h1a, s); \
    h = pair_min(hA, gv.z, gv.w, &h1b, s); \
    float4 o; \
    if (LIM) { \
        o.x = fminf(1.f, __fdividef(lt, fmaxf(sgn*h1a, 1e-7f))); \
        o.y = fminf(1.f, __fdividef(lt, fmaxf(sgn*hA , 1e-7f))); \
        o.z = fminf(1.f, __fdividef(lt, fmaxf(sgn*h1b, 1e-7f))); \
        o.w = fminf(1.f, __fdividef(lt, fmaxf(sgn*h  , 1e-7f))); \
    } else { o.x = sgn*h1a; o.y = sgn*hA; o.z = sgn*h1b; o.w = sgn*h; } \
    dp[jp*LNC] = o; }
    for (int bs = 0; bs < Q4C-16; bs += 16) {
#pragma unroll
        for (int j = 0; j < 16; ++j) {
            float4 gv = ring[j]; ring[j] = __ldg(sp4 + (bs + 16 + j)*LNC);
            int jp = bs + j;
            SQ
        }
    }
    { int bs = Q4C-16;
#pragma unroll
      for (int j = 0; j < 16; ++j) { float4 gv = ring[j]; int jp = bs + j; SQ } }
#undef SQ
}

// 48 blocks x 128 threads
__global__ void k_smooth_band(const float* __restrict__ atms, const float* __restrict__ rtms)
{
    int seq = blockIdx.x, c = threadIdx.x;      // c in [0,128)
    int band = seq >> 4, b = seq & 15;
    int idx = b*3 + band;
    float at = 1.f - __expf(-2200.f/(atms[idx]*44100.f));
    float rt = 1.f - __expf(-2200.f/(rtms[idx]*44100.f));
    float sgn = (at >= rt) ? 1.f : -1.f;
    SMC s = make_smc(at, rt);
    float R[9];
    {
        float tmp[9];
        float a1p = 1.f;
#pragma unroll
        for (int k = 0; k <= 8; ++k) { tmp[8-k] = a1p; a1p *= s.A1; }   // tmp[k] = A1^(8-k)
        float a2 = 1.f;
#pragma unroll
        for (int k = 0; k <= 8; ++k) { R[k] = tmp[k]*a2; a2 *= s.A2; }  // R[k] = A1^(8-k) A2^k
    }
    const float4* ma = g_m8a + (size_t)seq*G8;
    const float4* mb = g_m8b + (size_t)seq*G8;
    const float*  mc = g_m8c + (size_t)seq*G8;
    float h = sgn;    // f init = 1 (signed)
#pragma unroll 1
    for (int seg = 0; seg < SM_W; ++seg) {
        int cc = c - SM_W + seg;
        if (cc >= 0) h = warm8(ma + cc, mb + cc, mc + cc, h, R);
    }
    const float4* gin = (const float4*)(g_gin + (size_t)seq*T_LEN) + c;
    float4*       gsm = (float4*)(g_gsm + (size_t)seq*T_LEN) + c;
    store_seg<false>(gin, gsm, h, s, sgn, 0.f);
}

__global__ void k_smooth_lim(const float* __restrict__ lth, const float* __restrict__ lat,
                             const float* __restrict__ lrt)
{
    int b = blockIdx.x, c = threadIdx.x;        // c in [0,128)
    float at = 1.f - __expf(-2200.f/(lat[b]*44100.f));
    float rt = 1.f - __expf(-2200.f/(lrt[b]*44100.f));
    float sgn = (at <= rt) ? 1.f : -1.f;        // attack_on_rise=True -> min iff at<=rt
    float lt = exp2f(lth[b] * DB2L);
    SMC s = make_smc(at, rt);
    float R[9];
    {
        float tmp[9];
        float a1p = 1.f;
#pragma unroll
        for (int k = 0; k <= 8; ++k) { tmp[8-k] = a1p; a1p *= s.A1; }
        float a2 = 1.f;
#pragma unroll
        for (int k = 0; k <= 8; ++k) { R[k] = tmp[k]*a2; a2 *= s.A2; }
    }
    const float4* ma = g_l8a + (size_t)b*G8;
    const float4* mb = g_l8b + (size_t)b*G8;
    const float*  mc = g_l8c + (size_t)b*G8;
    float h = 0.f;    // f init = 0
#pragma unroll 1
    for (int seg = 0; seg < SM_W; ++seg) {
        int cc = c - SM_W + seg;
        if (cc >= 0) h = warm8(ma + cc, mb + cc, mc + cc, h, R);
    }
    const float4* det = (const float4*)(g_det + (size_t)b*T_LEN) + c;
    float4*       lg  = (float4*)(g_lg + (size_t)b*T_LEN) + c;
    store_seg<true>(det, lg, h, s, sgn, lt);
}

// ---------------- mix + SIGNED limiter detector ----------------
__global__ void k_mix(const float* __restrict__ mbmix, const float* __restrict__ lat,
                      const float* __restrict__ lrt)
{
    __shared__ float slsg;
    int b = blockIdx.y;
    int tid = threadIdx.x;
    if (tid == 0) {
        float at = 1.f - __expf(-2200.f/(lat[b]*44100.f));
        float rt = 1.f - __expf(-2200.f/(lrt[b]*44100.f));
        slsg = (at <= rt) ? 1.f : -1.f;
    }
    __syncthreads();
    float mb = __ldg(mbmix + b), om = 1.f - mb;
    int i = blockIdx.x * blockDim.x + tid;
    size_t p0 = (size_t)(b*2) * P4, p1 = p0 + P4;
    float4 x0 = ((const float4*)g_xd)[p0 + i],  x1 = ((const float4*)g_xd)[p1 + i];
    float4 l0 = ((const float4*)g_low)[p0 + i], l1 = ((const float4*)g_low)[p1 + i];
    float4 h0 = ((const float4*)g_high)[p0 + i],h1 = ((const float4*)g_high)[p1 + i];
    float4 gl = ((const float4*)g_gsm)[(size_t)(0*NB + b)*P4 + i];
    float4 gm = ((const float4*)g_gsm)[(size_t)(1*NB + b)*P4 + i];
    float4 gh = ((const float4*)g_gsm)[(size_t)(2*NB + b)*P4 + i];
    float sg = slsg;
    float4 m0, m1, dt;
#define ML(L) { \
    float mid0 = x0.L - l0.L - h0.L; \
    float y0 = l0.L*gl.L + mid0*gm.L + h0.L*gh.L; \
    float a0 = mb*y0 + om*x0.L; \
    float mid1 = x1.L - l1.L - h1.L; \
    float y1 = l1.L*gl.L + mid1*gm.L + h1.L*gh.L; \
    float a1 = mb*y1 + om*x1.L; \
    m0.L = a0; m1.L = a1; dt.L = sg*fabsf(a0 + a1); }
    ML(x) ML(y) ML(z) ML(w)
#undef ML
    ((float4*)g_xm)[p0 + i] = m0;
    ((float4*)g_xm)[p1 + i] = m1;
    ((float4*)g_det)[(size_t)b*P4 + i] = dt;
}

// ---------------- final: Q -> natural, apply limiter gain ----------------
__global__ void k_final(float* __restrict__ out)
{
    __shared__ float4 sA[32][33], sB[32][33];
    int b = blockIdx.y;
    int bx = blockIdx.x;
    int c0 = (bx >> 3) * 32, q0 = (bx & 7) * 32;
    int tx = threadIdx.x, ty = threadIdx.y;
    size_t A = (size_t)(q0 + ty) * LNC + c0 + tx;
    const float4* lg4 = (const float4*)g_lg + (size_t)b * P4;
    const float4* xm4 = (const float4*)g_xm;
    float4 g  = __ldg(lg4 + A);
    float4 m0 = __ldg(xm4 + (size_t)(b*2)   * P4 + A);
    float4 m1 = __ldg(xm4 + (size_t)(b*2+1) * P4 + A);
    m0.x *= g.x; m0.y *= g.y; m0.z *= g.z; m0.w *= g.w;
    m1.x *= g.x; m1.y *= g.y; m1.z *= g.z; m1.w *= g.w;
    sA[tx][ty] = m0;
    sB[tx][ty] = m1;
    __syncthreads();
    float4* o0 = (float4*)out + (size_t)(b*2) * P4;
    float4* o1 = o0 + P4;
    size_t N = (size_t)(c0 + ty) * Q4C + q0 + tx;
    o0[N] = sA[ty][tx];
    o1[N] = sB[ty][tx];
}

// ---------------- launcher ----------------
extern "C" void kernel_launch(void* const* d_in, const int* in_sizes, int n_in,
                              void* d_out, int out_size)
{
    const float* x     = (const float*)d_in[0];
    const float* drive = (const float*)d_in[1];
    const float* dmix  = (const float*)d_in[2];
    const float* locut = (const float*)d_in[3];
    const float* hicut = (const float*)d_in[4];
    const float* mbmix = (const float*)d_in[5];
    const float* ct    = (const float*)d_in[6];
    const float* cr    = (const float*)d_in[7];
    const float* et    = (const float*)d_in[8];
    const float* er    = (const float*)d_in[9];
    const float* atms  = (const float*)d_in[10];
    const float* rtms  = (const float*)d_in[11];
    const float* lth   = (const float*)d_in[12];
    const float* lat   = (const float*)d_in[13];
    const float* lrt   = (const float*)d_in[14];
    (void)in_sizes; (void)n_in; (void)out_size;

    dim3 tile(32, 32);
    k_dist<<<dim3(32, NSEQ), tile>>>(x, drive, dmix);
    k_bq<<<64, BQ_NT>>>(locut, hicut);
    k_bandgain<<<dim3(128, NB), 256>>>(ct, cr, et, er, atms, rtms);
    k_map8B<<<dim3(64, NBS), 256>>>(atms, rtms);
    k_smooth_band<<<NBS, LNC>>>(atms, rtms);
    k_mix<<<dim3(128, NB), 256>>>(mbmix, lat, lrt);
    k_map8L<<<dim3(64, NB), 256>>>(lat, lrt);
    k_smooth_lim<<<NB, LNC>>>(lth, lat, lrt);
    k_final<<<dim3(32, NB), tile>>>((float*)d_out);
}